// round 16
// baseline (speedup 1.0000x reference)
#include <cuda_runtime.h>
#include <math.h>

#define NJ 23
#define NP 16
#define TPB 64          // skin kernel threads per block
#define VPM 6           // vertices per thread
#define VPB (TPB*VPM)   // 384 vertices per block

// Transposed weights [NJ][V] and packed skinning matrices (pose pairs).
__device__ float g_wT[NJ * 500000];
__device__ float g_A2[NJ * 8 * 24];

__constant__ int c_par[NJ]  = {-1,0,1,1,3,4,5,4,7,4,9,1,11,12,13,12,15,12,17,0,19,0,21};
__constant__ int c_slot[NJ] = {0,-1,-1,1,2,3,-1,4,-1,5,-1,6,7,8,-1,9,-1,10,-1,-1,-1,-1,-1};
__constant__ float c_scale[11] = {
    0.7853981633974483f, 1.5707963267948966f, 1.5707963267948966f,
    0.7853981633974483f, 0.7853981633974483f, 0.7853981633974483f,
    1.5707963267948966f, 1.5707963267948966f, 0.7853981633974483f,
    0.7853981633974483f, 0.7853981633974483f};
__constant__ int c_lvl[NJ]  = {0,1,2,2,3,4,5,4,5,4,5,2,3,4,5,4,5,4,5,1,2,1,2};

struct Ptrs11 { const float* p[11]; };

// ---- f32x2 packed helpers (ptxas never emits these from C++) --------------
__device__ __forceinline__ void fma2(unsigned long long& d, unsigned long long a,
                                     unsigned long long b) {
    asm("fma.rn.f32x2 %0, %1, %2, %0;" : "+l"(d) : "l"(a), "l"(b));
}
__device__ __forceinline__ unsigned long long mul2(unsigned long long a,
                                                   unsigned long long b) {
    unsigned long long r;
    asm("mul.rn.f32x2 %0, %1, %2;" : "=l"(r) : "l"(a), "l"(b));
    return r;
}
__device__ __forceinline__ unsigned long long pack2(float lo, float hi) {
    unsigned long long r;
    asm("mov.b64 %0, {%1, %2};" : "=l"(r) : "f"(lo), "f"(hi));
    return r;
}
__device__ __forceinline__ void unpack2(unsigned long long v, float& lo, float& hi) {
    asm("mov.b64 {%0, %1}, %2;" : "=f"(lo), "=f"(hi) : "l"(v));
}

// ---------------------------------------------------------------------------
// Kernel 1: weight transpose (all blocks) + pose kinematics (block 0 only).
// buf aliases: pose uses [0:4416) = T, [4416:8832) = G; transpose then reuses
// [0:5888) as the 256x23 tile (after block 0's pose completes).
// ---------------------------------------------------------------------------
__global__ void prep_kernel(const float* __restrict__ w,
                            const float* __restrict__ joints,
                            const float* __restrict__ disp,
                            const float* __restrict__ rdis,
                            Ptrs11 prm,
                            float* __restrict__ out, int V)
{
    __shared__ float buf[8832];   // 35328 B
    int t = threadIdx.x;

    if (blockIdx.x == 0) {
        float* sT = buf;
        float* sG = buf + 4416;
        // Rodrigues + local transforms (368 tasks over 256 threads)
        #pragma unroll
        for (int k = 0; k < 2; k++) {
            int idx = t + k * 256;
            if (idx < NP * NJ) {
                int p = idx / NJ, jj = idx - p * NJ;
                int s = c_slot[jj];
                float rx = 0.f, ry = 0.f, rz = 0.f;
                if (s >= 0) {
                    const float* q = prm.p[s] + p * 3;
                    float sc = c_scale[s];
                    rx = sc * tanhf(q[0]); ry = sc * tanhf(q[1]); rz = sc * tanhf(q[2]);
                }
                float th = sqrtf(rx * rx + ry * ry + rz * rz + 1e-16f);
                float inv = 1.f / th;
                float ax = rx * inv, ay = ry * inv, az = rz * inv;
                float sn = sinf(th), cs = cosf(th), oc = 1.f - cs;
                float* T = &sT[idx * 12];
                T[0] = cs + oc * ax * ax;      T[1] = oc * ax * ay - sn * az; T[2]  = oc * ax * az + sn * ay;
                T[4] = oc * ax * ay + sn * az; T[5] = cs + oc * ay * ay;      T[6]  = oc * ay * az - sn * ax;
                T[8] = oc * ax * az - sn * ay; T[9] = oc * ay * az + sn * ax; T[10] = cs + oc * az * az;
                float relx = joints[jj * 3 + 0], rely = joints[jj * 3 + 1], relz = joints[jj * 3 + 2];
                if (jj > 0) {
                    int pa = c_par[jj];
                    relx -= joints[pa * 3 + 0];
                    rely -= joints[pa * 3 + 1];
                    relz -= joints[pa * 3 + 2];
                }
                T[3] = relx; T[7] = rely; T[11] = relz;
                if (jj == 0) {
                    float* G = &sG[(p * NJ) * 12];
                    #pragma unroll
                    for (int i = 0; i < 12; i++) G[i] = T[i];
                }
            }
        }
        __syncthreads();

        // Kinematic chain level-by-level (depth 5)
        #pragma unroll 1
        for (int l = 1; l <= 5; l++) {
            #pragma unroll
            for (int k = 0; k < 2; k++) {
                int idx = t + k * 256;
                if (idx < NP * NJ) {
                    int p = idx / NJ, jj = idx - p * NJ;
                    if (c_lvl[jj] == l) {
                        const float* Gp = &sG[(p * NJ + c_par[jj]) * 12];
                        const float* T  = &sT[idx * 12];
                        float* Gc = &sG[idx * 12];
                        #pragma unroll
                        for (int i = 0; i < 3; i++) {
                            float a0 = Gp[i * 4 + 0], a1 = Gp[i * 4 + 1], a2 = Gp[i * 4 + 2];
                            Gc[i * 4 + 0] = a0 * T[0] + a1 * T[4] + a2 * T[8];
                            Gc[i * 4 + 1] = a0 * T[1] + a1 * T[5] + a2 * T[9];
                            Gc[i * 4 + 2] = a0 * T[2] + a1 * T[6] + a2 * T[10];
                            Gc[i * 4 + 3] = a0 * T[3] + a1 * T[7] + a2 * T[11] + Gp[i * 4 + 3];
                        }
                    }
                }
            }
            __syncthreads();
        }

        // Pack A = [G_R | G_t - G_R@j + shift] -> g_A2; write posed joints.
        #pragma unroll
        for (int k = 0; k < 2; k++) {
            int idx = t + k * 256;
            if (idx < NP * NJ) {
                int p = idx / NJ, jj = idx - p * NJ;
                float sh0 = rdis[p * 3 + 0] + 3.f * tanhf(disp[p * 3 + 0]);
                float sh1 = rdis[p * 3 + 1] + 3.f * tanhf(disp[p * 3 + 1]);
                float sh2 = rdis[p * 3 + 2] + 3.f * tanhf(disp[p * 3 + 2]);
                const float* G = &sG[idx * 12];
                size_t jbase = (size_t)NP * V * 3 + ((size_t)p * NJ + jj) * 3;
                out[jbase + 0] = G[3]  + sh0;
                out[jbase + 1] = G[7]  + sh1;
                out[jbase + 2] = G[11] + sh2;
                float jx = joints[jj * 3 + 0], jy = joints[jj * 3 + 1], jz = joints[jj * 3 + 2];
                int pp = p >> 1, par = p & 1;
                float* dst = g_A2 + ((jj * 8 + pp) * 12) * 2 + par;
                float sh[3] = {sh0, sh1, sh2};
                #pragma unroll
                for (int i = 0; i < 3; i++) {
                    float tr = G[i * 4 + 3] - (G[i * 4 + 0] * jx + G[i * 4 + 1] * jy + G[i * 4 + 2] * jz) + sh[i];
                    dst[(i * 4 + 0) * 2] = G[i * 4 + 0];
                    dst[(i * 4 + 1) * 2] = G[i * 4 + 1];
                    dst[(i * 4 + 2) * 2] = G[i * 4 + 2];
                    dst[(i * 4 + 3) * 2] = tr;
                }
            }
        }
        __syncthreads();   // pose reads of buf done before tile reuse
    }

    // ---- weight transpose: [V, NJ] -> g_wT[NJ, V], one 256-vertex tile ----
    int base = blockIdx.x * 256;
    int n = V - base;
    if (n > 256) n = 256;
    if (n > 0) {
        int total = n * NJ;
        #pragma unroll 1
        for (int i = t; i < total; i += 256) buf[i] = w[(size_t)base * NJ + i];
        __syncthreads();
        if (t < n) {
            #pragma unroll
            for (int j = 0; j < NJ; j++)
                g_wT[(size_t)j * V + base + t] = buf[t * NJ + j];
        }
    }
}

// ---------------------------------------------------------------------------
// Kernel 2: skinning. 6 vertices/thread; A broadcast from smem (17.7 KB only)
// -> 8 CTAs/SM = 16 warps (4/SMSP). Weights read coalesced from g_wT (L2/L1).
// Pose pairs one per pass (8 passes): acc = 18 ULL regs.
// Per thread: 1104 LDS.128 : 13248 FFMA2 = 1:12.
// ---------------------------------------------------------------------------
__global__ void __launch_bounds__(TPB, 8)
skin_kernel(const float* __restrict__ verts,
            float* __restrict__ out, int V)
{
    __shared__ __align__(16) float sA[NJ * 8 * 24];   // 17664 B
    int t = threadIdx.x;

    {
        const float4* g4 = (const float4*)g_A2;
        float4* s4 = (float4*)sA;
        #pragma unroll 1
        for (int i = t; i < NJ * 8 * 24 / 4; i += TPB) s4[i] = g4[i];
    }
    __syncthreads();

    int base = blockIdx.x * VPB;
    int vc[VPM];
    unsigned long long cx[VPM], cy[VPM], cz[VPM];
    #pragma unroll
    for (int m = 0; m < VPM; m++) {
        int v = base + t + m * TPB;
        vc[m] = v < V ? v : V - 1;
        float x = verts[3 * vc[m] + 0];
        float y = verts[3 * vc[m] + 1];
        float z = verts[3 * vc[m] + 2];
        cx[m] = pack2(x, x); cy[m] = pack2(y, y); cz[m] = pack2(z, z);
    }
    size_t slabsz = (size_t)V * 3;

    #pragma unroll 1
    for (int pp = 0; pp < 8; pp++) {
        unsigned long long acc[VPM][3];
        #pragma unroll
        for (int m = 0; m < VPM; m++) {
            acc[m][0] = 0ull; acc[m][1] = 0ull; acc[m][2] = 0ull;
        }

        #pragma unroll 1
        for (int j = 0; j < NJ; j++) {
            const ulonglong2* r = (const ulonglong2*)(sA + (j * 8 + pp) * 24);
            ulonglong2 q0 = r[0], q1 = r[1], q2 = r[2];
            ulonglong2 q3 = r[3], q4 = r[4], q5 = r[5];
            const float* wr = g_wT + (size_t)j * V;
            #pragma unroll
            for (int m = 0; m < VPM; m++) {
                float wv = __ldg(wr + vc[m]);
                unsigned long long wp = pack2(wv, wv);
                unsigned long long ax = mul2(wp, cx[m]);
                unsigned long long ay = mul2(wp, cy[m]);
                unsigned long long az = mul2(wp, cz[m]);
                fma2(acc[m][0], q0.x, ax); fma2(acc[m][0], q0.y, ay);
                fma2(acc[m][0], q1.x, az); fma2(acc[m][0], q1.y, wp);
                fma2(acc[m][1], q2.x, ax); fma2(acc[m][1], q2.y, ay);
                fma2(acc[m][1], q3.x, az); fma2(acc[m][1], q3.y, wp);
                fma2(acc[m][2], q4.x, ax); fma2(acc[m][2], q4.y, ay);
                fma2(acc[m][2], q5.x, az); fma2(acc[m][2], q5.y, wp);
            }
        }

        size_t c0 = (size_t)(2 * pp) * slabsz;
        #pragma unroll
        for (int m = 0; m < VPM; m++) {
            int v = base + t + m * TPB;
            if (v < V) {
                size_t vb = (size_t)v * 3;
                float lo, hi;
                unpack2(acc[m][0], lo, hi);
                out[c0 + vb + 0] = lo; out[c0 + slabsz + vb + 0] = hi;
                unpack2(acc[m][1], lo, hi);
                out[c0 + vb + 1] = lo; out[c0 + slabsz + vb + 1] = hi;
                unpack2(acc[m][2], lo, hi);
                out[c0 + vb + 2] = lo; out[c0 + slabsz + vb + 2] = hi;
            }
        }
    }
}

// ---------------------------------------------------------------------------
// Launch: prep (transpose + pose), then skin.
// ---------------------------------------------------------------------------
extern "C" void kernel_launch(void* const* d_in, const int* in_sizes, int n_in,
                              void* d_out, int out_size)
{
    const float* verts   = (const float*)d_in[0];
    const float* joints  = (const float*)d_in[1];
    const float* weights = (const float*)d_in[2];
    const float* disp    = (const float*)d_in[3];
    const float* rdis    = (const float*)d_in[4];
    Ptrs11 prm;
    for (int i = 0; i < 11; i++) prm.p[i] = (const float*)d_in[5 + i];
    int V = in_sizes[0] / 3;
    float* out = (float*)d_out;

    int nb1 = (V + 255) / 256;
    prep_kernel<<<nb1, 256>>>(weights, joints, disp, rdis, prm, out, V);
    int nb2 = (V + VPB - 1) / VPB;
    skin_kernel<<<nb2, TPB>>>(verts, out, V);
}